// round 1
// baseline (speedup 1.0000x reference)
#include <cuda_runtime.h>
#include <math.h>

#define D_MODEL 4096
#define D_IN1   4112
#define D_CTRL  64
#define BATCH   4
#define SEQ     2048
#define BS_TOT  (BATCH * SEQ)   // 8192

typedef unsigned long long ull;

// -------- scratch (no allocation allowed; device globals) --------
__device__ __align__(16) float g_weff[D_CTRL * D_MODEL];  // 1 MB
__device__ __align__(16) float g_delta[BS_TOT];

// -------- helpers --------
__device__ __forceinline__ ull dup2(float x) {
    ull r;
    asm("mov.b64 %0, {%1, %1};" : "=l"(r) : "f"(x));
    return r;
}
__device__ __forceinline__ void ffma2(ull &d, ull a, ull b) {
    asm("fma.rn.f32x2 %0, %1, %2, %0;" : "+l"(d) : "l"(a), "l"(b));
}
__device__ __forceinline__ ull addf2(ull a, ull b) {
    ull r;
    asm("add.rn.f32x2 %0, %1, %2;" : "=l"(r) : "l"(a), "l"(b));
    return r;
}
__device__ __forceinline__ float lo32(ull v) { return __uint_as_float((unsigned)(v & 0xffffffffu)); }
__device__ __forceinline__ float hi32(ull v) { return __uint_as_float((unsigned)(v >> 32)); }

__device__ __forceinline__ float gelu_exact(float x) {
    return 0.5f * x * (1.0f + erff(x * 0.7071067811865476f));
}
__device__ __forceinline__ float softplus_f(float x) {
    return fmaxf(x, 0.0f) + log1pf(expf(-fabsf(x)));
}

// ============================================================
// Kernel 1: Weff[k][d] = W1[k][d] + sum_f W1[k][4096+f] * Wf[f][d]
// grid (D_MODEL/256, 64), block 256
// ============================================================
__global__ void weff_kernel(const float* __restrict__ W1,
                            const float* __restrict__ Wf) {
    __shared__ float tail[16];
    const int k = blockIdx.y;
    if (threadIdx.x < 16) tail[threadIdx.x] = W1[k * D_IN1 + D_MODEL + threadIdx.x];
    __syncthreads();
    const int d = blockIdx.x * 256 + threadIdx.x;
    float v = W1[k * D_IN1 + d];
#pragma unroll
    for (int f = 0; f < 16; ++f)
        v = fmaf(tail[f], Wf[f * D_MODEL + d], v);
    g_weff[k * D_MODEL + d] = v;
}

// ============================================================
// Kernel 2: fused GEMM [BS,4096]x[4096,64] + bias + GELU + W2 + softplus
// block: 256 threads = 4 K-slices x 64 threads; each thread: 8m x 8n f32x2 tile
// TM=64, TN=64, BK=16, K per slice = 1024, 64 chunks
// grid: BS_TOT/64 = 128
// ============================================================
__global__ void __launch_bounds__(256)
fused_gemm_kernel(const float* __restrict__ hidden,
                  const float* __restrict__ b1,
                  const float* __restrict__ W2,
                  const float* __restrict__ b2) {
    __shared__ __align__(16) float As[4][16][68];
    __shared__ __align__(16) float Bs[4][16][68];

    const int tid = threadIdx.x;
    const int sl  = tid >> 6;          // K slice 0..3
    const int ts  = tid & 63;          // thread within slice
    const int tm  = ts >> 3;           // 0..7
    const int tn  = ts & 7;            // 0..7
    const int m0  = tm * 8;
    const int n0  = tn * 8;
    const int rowbase = blockIdx.x * 64;

    const int q    = ts & 3;           // staging col-quad (16 cols / 4)
    const int srow = ts >> 2;          // staging base row 0..15
    const int kbase = sl * 1024;

    ull acc[4][8];
#pragma unroll
    for (int i = 0; i < 4; ++i)
#pragma unroll
        for (int j = 0; j < 8; ++j) acc[i][j] = 0ULL;

    float4 pa[4], pb[4];
    // prefetch chunk 0
    {
        const int kc = kbase;
#pragma unroll
        for (int rr = 0; rr < 4; ++rr) {
            const int r = srow + rr * 16;
            pa[rr] = *(const float4*)&hidden[(size_t)(rowbase + r) * D_MODEL + kc + q * 4];
            pb[rr] = *(const float4*)&g_weff[(size_t)r * D_MODEL + kc + q * 4];
        }
    }

    for (int c = 0; c < 64; ++c) {
        // store staged registers to smem (A and B transposed to [k][row])
#pragma unroll
        for (int rr = 0; rr < 4; ++rr) {
            const int r = srow + rr * 16;
            As[sl][q * 4 + 0][r] = pa[rr].x;
            As[sl][q * 4 + 1][r] = pa[rr].y;
            As[sl][q * 4 + 2][r] = pa[rr].z;
            As[sl][q * 4 + 3][r] = pa[rr].w;
            Bs[sl][q * 4 + 0][r] = pb[rr].x;
            Bs[sl][q * 4 + 1][r] = pb[rr].y;
            Bs[sl][q * 4 + 2][r] = pb[rr].z;
            Bs[sl][q * 4 + 3][r] = pb[rr].w;
        }
        __syncthreads();

        // prefetch next chunk (hidden behind compute)
        if (c + 1 < 64) {
            const int kc = kbase + (c + 1) * 16;
#pragma unroll
            for (int rr = 0; rr < 4; ++rr) {
                const int r = srow + rr * 16;
                pa[rr] = *(const float4*)&hidden[(size_t)(rowbase + r) * D_MODEL + kc + q * 4];
                pb[rr] = *(const float4*)&g_weff[(size_t)r * D_MODEL + kc + q * 4];
            }
        }

#pragma unroll
        for (int kk = 0; kk < 16; ++kk) {
            ulonglong2 a01 = *(const ulonglong2*)&As[sl][kk][m0];
            ulonglong2 a23 = *(const ulonglong2*)&As[sl][kk][m0 + 4];
            float4 bA = *(const float4*)&Bs[sl][kk][n0];
            float4 bB = *(const float4*)&Bs[sl][kk][n0 + 4];
            ull bb[8];
            bb[0] = dup2(bA.x); bb[1] = dup2(bA.y); bb[2] = dup2(bA.z); bb[3] = dup2(bA.w);
            bb[4] = dup2(bB.x); bb[5] = dup2(bB.y); bb[6] = dup2(bB.z); bb[7] = dup2(bB.w);
            ull ap[4] = {a01.x, a01.y, a23.x, a23.y};
#pragma unroll
            for (int mp = 0; mp < 4; ++mp)
#pragma unroll
                for (int j = 0; j < 8; ++j)
                    ffma2(acc[mp][j], ap[mp], bb[j]);
        }
        __syncthreads();
    }

    // -------- cross-slice reduction (slices 1..3 fold into slice 0) --------
    ull* r0 = (ull*)&As[0][0][0];  // 2176 ull capacity, need 2048
    ull* r1 = (ull*)&Bs[0][0][0];

    if (sl == 2) {
#pragma unroll
        for (int mp = 0; mp < 4; ++mp)
#pragma unroll
            for (int j = 0; j < 8; ++j) r0[(mp * 8 + j) * 64 + ts] = acc[mp][j];
    }
    if (sl == 3) {
#pragma unroll
        for (int mp = 0; mp < 4; ++mp)
#pragma unroll
            for (int j = 0; j < 8; ++j) r1[(mp * 8 + j) * 64 + ts] = acc[mp][j];
    }
    __syncthreads();
    if (sl == 0) {
#pragma unroll
        for (int mp = 0; mp < 4; ++mp)
#pragma unroll
            for (int j = 0; j < 8; ++j)
                acc[mp][j] = addf2(acc[mp][j], r0[(mp * 8 + j) * 64 + ts]);
    }
    if (sl == 1) {
#pragma unroll
        for (int mp = 0; mp < 4; ++mp)
#pragma unroll
            for (int j = 0; j < 8; ++j)
                acc[mp][j] = addf2(acc[mp][j], r1[(mp * 8 + j) * 64 + ts]);
    }
    __syncthreads();
    if (sl == 1) {
#pragma unroll
        for (int mp = 0; mp < 4; ++mp)
#pragma unroll
            for (int j = 0; j < 8; ++j) r0[(mp * 8 + j) * 64 + ts] = acc[mp][j];
    }
    __syncthreads();

    if (sl == 0) {
        float b1r[8], w2r[8];
#pragma unroll
        for (int j = 0; j < 8; ++j) {
            b1r[j] = b1[n0 + j];
            w2r[j] = W2[n0 + j];
        }
        const float b2v = b2[0];

        float p[8];
#pragma unroll
        for (int mp = 0; mp < 4; ++mp) {
            float plo = 0.f, phi = 0.f;
#pragma unroll
            for (int j = 0; j < 8; ++j) {
                ull v = addf2(acc[mp][j], r0[(mp * 8 + j) * 64 + ts]);
                plo += gelu_exact(lo32(v) + b1r[j]) * w2r[j];
                phi += gelu_exact(hi32(v) + b1r[j]) * w2r[j];
            }
            p[2 * mp + 0] = plo;
            p[2 * mp + 1] = phi;
        }
        // reduce over the 8 tn lanes (segments of 8 within the warp)
#pragma unroll
        for (int i = 0; i < 8; ++i) {
            float v = p[i];
            v += __shfl_xor_sync(0xffffffffu, v, 1, 8);
            v += __shfl_xor_sync(0xffffffffu, v, 2, 8);
            v += __shfl_xor_sync(0xffffffffu, v, 4, 8);
            p[i] = v;
        }
        if (tn == 0) {
#pragma unroll
            for (int i = 0; i < 8; ++i)
                g_delta[rowbase + m0 + i] = softplus_f(p[i] + b2v);
        }
    }
}

// ============================================================
// Kernel 3: mean(delta) + causal EMA scan + gate/field outputs
// single block, 256 threads; warps 0..3 handle batches 0..3
// out layout: [0,8192) gate, [8192,16384) field, [16384] mean
// ============================================================
__global__ void ema_kernel(const float* __restrict__ lam_p,
                           float* __restrict__ out) {
    __shared__ float red[256];
    const int tid = threadIdx.x;

    float s = 0.f;
    for (int i = tid; i < BS_TOT; i += 256) s += g_delta[i];
    red[tid] = s;
    __syncthreads();
    for (int off = 128; off > 0; off >>= 1) {
        if (tid < off) red[tid] += red[tid + off];
        __syncthreads();
    }
    if (tid == 0) out[2 * BS_TOT] = red[0] * (1.0f / (float)BS_TOT);

    const int w = tid >> 5, lane = tid & 31;
    if (w < BATCH) {
        const float lam   = lam_p[0];
        const float alpha = 0.9f;
        const float apl   = powf(alpha, (float)lane);   // a^lane
        const float ainv  = powf(alpha, -(float)lane);  // a^-lane
        const float apl1  = apl * alpha;                // a^(lane+1)
        float h = 0.f;
        const float* drow = g_delta + w * SEQ;
        float* gate = out + w * SEQ;
        float* fld  = out + BS_TOT + w * SEQ;

        for (int c = 0; c < SEQ / 32; ++c) {
            const float d = drow[c * 32 + lane];
            float t = 0.1f * d * ainv;  // c_i * a^{-i}
#pragma unroll
            for (int off = 1; off < 32; off <<= 1) {
                float v = __shfl_up_sync(0xffffffffu, t, off);
                if (lane >= off) t += v;
            }
            const float x = fmaf(apl1, h, t * apl);  // a^{i+1} h_base + s_i
            fld[c * 32 + lane]  = x;
            gate[c * 32 + lane] = 1.0f / (1.0f + expf(lam * x));
            h = __shfl_sync(0xffffffffu, x, 31);     // x_31 = new carry
        }
    }
}

// ============================================================
extern "C" void kernel_launch(void* const* d_in, const int* in_sizes, int n_in,
                              void* d_out, int out_size) {
    const float* hidden = (const float*)d_in[0];
    const float* Wf     = (const float*)d_in[1];
    const float* W1     = (const float*)d_in[2];
    const float* b1     = (const float*)d_in[3];
    const float* W2     = (const float*)d_in[4];
    const float* b2     = (const float*)d_in[5];
    const float* lam    = (const float*)d_in[6];
    float* out = (float*)d_out;

    weff_kernel<<<dim3(D_MODEL / 256, D_CTRL), 256>>>(W1, Wf);
    fused_gemm_kernel<<<BS_TOT / 64, 256>>>(hidden, b1, W2, b2);
    ema_kernel<<<1, 256>>>(lam, out);
}

// round 3
// speedup vs baseline: 2.1368x; 2.1368x over previous
#include <cuda_runtime.h>
#include <math.h>
#include <stdint.h>

#define D_MODEL 4096
#define D_IN1   4112
#define D_CTRL  64
#define BATCH   4
#define SEQ     2048
#define BS_TOT  8192

// ---------------- GEMM tiling ----------------
#define MTILE    128
#define KSPLIT   4
#define KPER     (D_MODEL / KSPLIT)     // 1024
#define KC       32                     // floats per chunk
#define NCHUNK   (KPER / KC)            // 32
#define NST      3
#define ROWF     36                     // padded row stride in floats (144 B, 16B-aligned)
#define ASTGF    (MTILE * ROWF)         // 4608 floats
#define BSTGF    (D_CTRL * ROWF)        // 2304 floats
#define B_OFFF   (NST * ASTGF)          // 13824
#define SMEM_FLOATS (B_OFFF + NST * BSTGF)  // 20736 floats = 82944 B

__device__ __align__(16) float g_weff[D_CTRL * D_MODEL];          // 1 MiB
__device__ __align__(16) float g_partial[BS_TOT * KSPLIT * D_CTRL]; // 8 MiB
__device__ __align__(16) float g_delta[BS_TOT];

// ---------------- helpers ----------------
__device__ __forceinline__ uint32_t smem_u32(const void* p) {
    uint32_t a;
    asm("{ .reg .u64 t; cvta.to.shared.u64 t, %1; cvt.u32.u64 %0, t; }" : "=r"(a) : "l"(p));
    return a;
}
__device__ __forceinline__ void cp16(uint32_t dst, const void* src) {
    asm volatile("cp.async.cg.shared.global [%0], [%1], 16;" :: "r"(dst), "l"(src));
}
__device__ __forceinline__ void mma_tf32(float* d, const uint32_t* a, const uint32_t* b) {
    asm volatile(
        "mma.sync.aligned.m16n8k8.row.col.f32.tf32.tf32.f32 "
        "{%0,%1,%2,%3}, {%4,%5,%6,%7}, {%8,%9}, {%0,%1,%2,%3};"
        : "+f"(d[0]), "+f"(d[1]), "+f"(d[2]), "+f"(d[3])
        : "r"(a[0]), "r"(a[1]), "r"(a[2]), "r"(a[3]), "r"(b[0]), "r"(b[1]));
}
__device__ __forceinline__ float gelu_exact(float x) {
    return 0.5f * x * (1.0f + erff(x * 0.7071067811865476f));
}
__device__ __forceinline__ float softplus_f(float x) {
    return fmaxf(x, 0.0f) + log1pf(expf(-fabsf(x)));
}

// ============================================================
// Kernel 1: Weff = W1[:, :4096] + W1[:, 4096:] @ W_fiber
// ============================================================
__global__ void weff_kernel(const float* __restrict__ W1,
                            const float* __restrict__ Wf) {
    __shared__ float tail[16];
    const int k = blockIdx.y;
    if (threadIdx.x < 16) tail[threadIdx.x] = W1[(size_t)k * D_IN1 + D_MODEL + threadIdx.x];
    __syncthreads();
    const int d4 = blockIdx.x * 256 + threadIdx.x;
    float4 v = *(const float4*)&W1[(size_t)k * D_IN1 + d4 * 4];
#pragma unroll
    for (int f = 0; f < 16; ++f) {
        float4 wf = *(const float4*)&Wf[(size_t)f * D_MODEL + d4 * 4];
        float t = tail[f];
        v.x = fmaf(t, wf.x, v.x);
        v.y = fmaf(t, wf.y, v.y);
        v.z = fmaf(t, wf.z, v.z);
        v.w = fmaf(t, wf.w, v.w);
    }
    *(float4*)&g_weff[(size_t)k * D_MODEL + d4 * 4] = v;
}

// ============================================================
// Kernel 2: split-K tf32 mma.sync GEMM -> g_partial
// grid (64, 4), 128 threads (4 warps), warp = 32 rows x 64 cols
// ============================================================
__global__ void __launch_bounds__(128, 2)
gemm_mma_kernel(const float* __restrict__ hidden) {
    extern __shared__ float sm[];
    const uint32_t sb = smem_u32(sm);

    const int tid = threadIdx.x;
    const int w   = tid >> 5;
    const int lane = tid & 31;
    const int g   = lane >> 2;     // groupID
    const int tig = lane & 3;      // thread-in-group
    const int rowbase = blockIdx.x * MTILE;
    const int ks      = blockIdx.y;
    const int kbase   = ks * KPER;

    float acc[2][8][4];
#pragma unroll
    for (int t = 0; t < 2; ++t)
#pragma unroll
        for (int n = 0; n < 8; ++n)
#pragma unroll
            for (int j = 0; j < 4; ++j) acc[t][n][j] = 0.0f;

    // per-thread load assignments
    const float* gA = hidden + (size_t)(rowbase + tid) * D_MODEL + kbase;
    const uint32_t aDst0 = sb + (uint32_t)tid * (ROWF * 4);
    const int bn   = tid >> 1;
    const int bh   = tid & 1;
    const float* gB = g_weff + (size_t)bn * D_MODEL + kbase + bh * 16;
    const uint32_t bDst0 = sb + (uint32_t)(B_OFFF + bn * ROWF + bh * 16) * 4;

    // prologue: stages 0..2
#pragma unroll
    for (int s = 0; s < NST; ++s) {
        const uint32_t aD = aDst0 + s * (ASTGF * 4);
        const uint32_t bD = bDst0 + s * (BSTGF * 4);
        const float* aS = gA + s * KC;
        const float* bS = gB + s * KC;
#pragma unroll
        for (int q = 0; q < 8; ++q) cp16(aD + q * 16, aS + q * 4);
#pragma unroll
        for (int j = 0; j < 4; ++j) cp16(bD + j * 16, bS + j * 4);
        asm volatile("cp.async.commit_group;" ::: "memory");
    }

    const uint32_t* smu = (const uint32_t*)sm;

    for (int c = 0; c < NCHUNK; ++c) {
        const int s = c % NST;
        asm volatile("cp.async.wait_group 2;" ::: "memory");
        __syncthreads();

        // compute chunk c from stage s
        const int abase = s * ASTGF + w * 32 * ROWF;
        const int bbase = B_OFFF + s * BSTGF;
#pragma unroll
        for (int kk = 0; kk < 4; ++kk) {
            const int k0 = kk * 8 + tig;
            uint32_t a[2][4];
#pragma unroll
            for (int t = 0; t < 2; ++t) {
                const int r0 = abase + (16 * t + g) * ROWF + k0;
                a[t][0] = smu[r0];
                a[t][2] = smu[r0 + 4];
                a[t][1] = smu[r0 + 8 * ROWF];
                a[t][3] = smu[r0 + 8 * ROWF + 4];
            }
            uint32_t b[8][2];
#pragma unroll
            for (int n = 0; n < 8; ++n) {
                const int r0 = bbase + (8 * n + g) * ROWF + k0;
                b[n][0] = smu[r0];
                b[n][1] = smu[r0 + 4];
            }
#pragma unroll
            for (int t = 0; t < 2; ++t)
#pragma unroll
                for (int n = 0; n < 8; ++n)
                    mma_tf32(acc[t][n], a[t], b[n]);
        }
        __syncthreads();

        // issue chunk c+NST into slot s (just freed)
        const int cn = c + NST;
        if (cn < NCHUNK) {
            const uint32_t aD = aDst0 + s * (ASTGF * 4);
            const uint32_t bD = bDst0 + s * (BSTGF * 4);
            const float* aS = gA + cn * KC;
            const float* bS = gB + cn * KC;
#pragma unroll
            for (int q = 0; q < 8; ++q) cp16(aD + q * 16, aS + q * 4);
#pragma unroll
            for (int j = 0; j < 4; ++j) cp16(bD + j * 16, bS + j * 4);
        }
        asm volatile("cp.async.commit_group;" ::: "memory");
    }

    // write partials: [row][ks][col]
#pragma unroll
    for (int t = 0; t < 2; ++t) {
        const int row0 = rowbase + w * 32 + 16 * t + g;
#pragma unroll
        for (int n = 0; n < 8; ++n) {
            const int col = 8 * n + 2 * tig;
            float2 v0 = make_float2(acc[t][n][0], acc[t][n][1]);
            float2 v1 = make_float2(acc[t][n][2], acc[t][n][3]);
            *(float2*)&g_partial[((size_t)row0 * 4 + ks) * 64 + col] = v0;
            *(float2*)&g_partial[((size_t)(row0 + 8) * 4 + ks) * 64 + col] = v1;
        }
    }
}

// ============================================================
// Kernel 3: reduce split-K partials + GELU dot W2 + softplus -> g_delta
// 1024 blocks x 256 threads; warp per row
// ============================================================
__global__ void __launch_bounds__(256)
reduce_kernel(const float* __restrict__ b1,
              const float* __restrict__ W2,
              const float* __restrict__ b2) {
    const int w = threadIdx.x >> 5, lane = threadIdx.x & 31;
    const int row = blockIdx.x * 8 + w;
    const int col = 2 * lane;

    float2 s = make_float2(0.0f, 0.0f);
#pragma unroll
    for (int ks = 0; ks < KSPLIT; ++ks) {
        float2 p = *(const float2*)&g_partial[((size_t)row * 4 + ks) * 64 + col];
        s.x += p.x;
        s.y += p.y;
    }
    float v = gelu_exact(s.x + b1[col]) * W2[col]
            + gelu_exact(s.y + b1[col + 1]) * W2[col + 1];
#pragma unroll
    for (int off = 16; off > 0; off >>= 1)
        v += __shfl_xor_sync(0xffffffffu, v, off);
    if (lane == 0) g_delta[row] = softplus_f(v + b2[0]);
}

// ============================================================
// Kernel 4: mean + causal EMA + gate
// ============================================================
__global__ void ema_kernel(const float* __restrict__ lam_p,
                           float* __restrict__ out) {
    __shared__ float warpsum[4];
    const int w = threadIdx.x >> 5, lane = threadIdx.x & 31;
    const float alpha = 0.9f, onem = 0.1f;
    const float A64 = powf(alpha, 64.0f);

    float d[64];
    const float4* dv = (const float4*)(g_delta + w * SEQ + lane * 64);
#pragma unroll
    for (int q = 0; q < 16; ++q) {
        float4 x = dv[q];
        d[4 * q + 0] = x.x; d[4 * q + 1] = x.y; d[4 * q + 2] = x.z; d[4 * q + 3] = x.w;
    }

    float s = 0.0f, sum = 0.0f;
#pragma unroll
    for (int j = 0; j < 64; ++j) { s = fmaf(alpha, s, onem * d[j]); sum += d[j]; }
#pragma unroll
    for (int off = 16; off > 0; off >>= 1) sum += __shfl_xor_sync(0xffffffffu, sum, off);
    if (lane == 0) warpsum[w] = sum;

    float t = s, Ak = A64;
#pragma unroll
    for (int off = 1; off < 32; off <<= 1) {
        float v = __shfl_up_sync(0xffffffffu, t, off);
        if (lane >= off) t = fmaf(Ak, v, t);
        Ak *= Ak;
    }
    float tp = __shfl_up_sync(0xffffffffu, t, 1);
    float h = (lane == 0) ? 0.0f : tp;

    const float lam = lam_p[0];
    float* gate = out + w * SEQ + lane * 64;
    float* fld  = out + BS_TOT + w * SEQ + lane * 64;
#pragma unroll
    for (int j = 0; j < 64; ++j) {
        h = fmaf(alpha, h, onem * d[j]);
        fld[j]  = h;
        gate[j] = 1.0f / (1.0f + expf(lam * h));
    }

    __syncthreads();
    if (threadIdx.x == 0)
        out[2 * BS_TOT] = (warpsum[0] + warpsum[1] + warpsum[2] + warpsum[3]) * (1.0f / (float)BS_TOT);
}

// ============================================================
extern "C" void kernel_launch(void* const* d_in, const int* in_sizes, int n_in,
                              void* d_out, int out_size) {
    const float* hidden = (const float*)d_in[0];
    const float* Wf     = (const float*)d_in[1];
    const float* W1     = (const float*)d_in[2];
    const float* b1     = (const float*)d_in[3];
    const float* W2     = (const float*)d_in[4];
    const float* b2     = (const float*)d_in[5];
    const float* lam    = (const float*)d_in[6];
    float* out = (float*)d_out;

    static int inited = 0;
    if (!inited) {
        cudaFuncSetAttribute(gemm_mma_kernel,
                             cudaFuncAttributeMaxDynamicSharedMemorySize,
                             SMEM_FLOATS * 4);
        inited = 1;
    }

    weff_kernel<<<dim3(4, D_CTRL), 256>>>(W1, Wf);
    gemm_mma_kernel<<<dim3(BS_TOT / MTILE, KSPLIT), 128, SMEM_FLOATS * 4>>>(hidden);
    reduce_kernel<<<BS_TOT / 8, 256>>>(b1, W2, b2);
    ema_kernel<<<1, 128>>>(lam, out);
}

// round 4
// speedup vs baseline: 2.7604x; 1.2918x over previous
#include <cuda_runtime.h>
#include <cuda_bf16.h>
#include <math.h>
#include <stdint.h>

#define D_MODEL 4096
#define D_IN1   4112
#define D_CTRL  64
#define BATCH   4
#define SEQ     2048
#define BS_TOT  8192

// ---------------- GEMM tiling ----------------
#define MTILE    128
#define KSPLIT   4
#define KPER     (D_MODEL / KSPLIT)     // 1024
#define KC       32                     // k elems per chunk
#define NCHUNK   (KPER / KC)            // 32
#define NST      3
#define AROWF    40                     // A row stride (floats)
#define BROWH    40                     // B row stride (bf16)
#define A_STG_B  (MTILE * AROWF * 4)    // 20480 B
#define B_STG_B  (D_CTRL * BROWH * 2)   // 5120 B
#define B_BASE_B (NST * A_STG_B)        // 61440
#define SMEM_B   (B_BASE_B + NST * B_STG_B)  // 76800

__device__ __align__(16) __nv_bfloat16 g_weff[D_CTRL * D_MODEL];   // 512 KiB
__device__ __align__(16) float g_partial[BS_TOT * KSPLIT * D_CTRL]; // 8 MiB
__device__ __align__(16) float g_delta[BS_TOT];

// ---------------- helpers ----------------
__device__ __forceinline__ uint32_t smem_u32(const void* p) {
    uint32_t a;
    asm("{ .reg .u64 t; cvta.to.shared.u64 t, %1; cvt.u32.u64 %0, t; }" : "=r"(a) : "l"(p));
    return a;
}
__device__ __forceinline__ void cp16(uint32_t dst, const void* src) {
    asm volatile("cp.async.cg.shared.global [%0], [%1], 16;" :: "r"(dst), "l"(src));
}
__device__ __forceinline__ uint32_t pack_bf16(float hi, float lo) {
    uint32_t r;
    asm("cvt.rn.bf16x2.f32 %0, %1, %2;" : "=r"(r) : "f"(hi), "f"(lo));
    return r;
}
__device__ __forceinline__ void mma_bf16(float* d, const uint32_t* a, const uint32_t* b) {
    asm volatile(
        "mma.sync.aligned.m16n8k16.row.col.f32.bf16.bf16.f32 "
        "{%0,%1,%2,%3}, {%4,%5,%6,%7}, {%8,%9}, {%0,%1,%2,%3};"
        : "+f"(d[0]), "+f"(d[1]), "+f"(d[2]), "+f"(d[3])
        : "r"(a[0]), "r"(a[1]), "r"(a[2]), "r"(a[3]), "r"(b[0]), "r"(b[1]));
}
__device__ __forceinline__ float gelu_exact(float x) {
    return 0.5f * x * (1.0f + erff(x * 0.7071067811865476f));
}
__device__ __forceinline__ float softplus_f(float x) {
    return fmaxf(x, 0.0f) + log1pf(expf(-fabsf(x)));
}

// ============================================================
// Kernel 1: Weff (bf16) = W1[:, :4096] + W1[:, 4096:] @ W_fiber
// grid (4, 64), block 256
// ============================================================
__global__ void weff_kernel(const float* __restrict__ W1,
                            const float* __restrict__ Wf) {
    __shared__ float tail[16];
    const int k = blockIdx.y;
    if (threadIdx.x < 16) tail[threadIdx.x] = W1[(size_t)k * D_IN1 + D_MODEL + threadIdx.x];
    __syncthreads();
    const int d4 = blockIdx.x * 256 + threadIdx.x;
    float4 v = *(const float4*)&W1[(size_t)k * D_IN1 + d4 * 4];
#pragma unroll
    for (int f = 0; f < 16; ++f) {
        float4 wf = *(const float4*)&Wf[(size_t)f * D_MODEL + d4 * 4];
        float t = tail[f];
        v.x = fmaf(t, wf.x, v.x);
        v.y = fmaf(t, wf.y, v.y);
        v.z = fmaf(t, wf.z, v.z);
        v.w = fmaf(t, wf.w, v.w);
    }
    uint2 pk;
    pk.x = pack_bf16(v.y, v.x);
    pk.y = pack_bf16(v.w, v.z);
    *(uint2*)&g_weff[(size_t)k * D_MODEL + d4 * 4] = pk;
}

// ============================================================
// Kernel 2: split-K bf16 mma.sync GEMM -> g_partial
// grid (64, 4), 128 threads (4 warps), warp = 32 rows x 64 cols
// A fp32 in smem (cvt in-register), B bf16 in smem
// ============================================================
__global__ void __launch_bounds__(128, 2)
gemm_mma_kernel(const float* __restrict__ hidden) {
    extern __shared__ char smc[];
    const uint32_t sb = smem_u32(smc);
    const float* smA = (const float*)smc;
    const uint32_t* smBu = (const uint32_t*)(smc + B_BASE_B);

    const int tid = threadIdx.x;
    const int w    = tid >> 5;
    const int lane = tid & 31;
    const int g    = lane >> 2;
    const int tig  = lane & 3;
    const int rowbase = blockIdx.x * MTILE;
    const int ks      = blockIdx.y;
    const int kbase   = ks * KPER;

    float acc[2][8][4];
#pragma unroll
    for (int t = 0; t < 2; ++t)
#pragma unroll
        for (int n = 0; n < 8; ++n)
#pragma unroll
            for (int j = 0; j < 4; ++j) acc[t][n][j] = 0.0f;

    // load assignments
    const float* gA = hidden + (size_t)(rowbase + tid) * D_MODEL + kbase;
    const uint32_t aDst0 = sb + (uint32_t)tid * (AROWF * 4);
    const int bn = tid >> 1;
    const int bh = tid & 1;
    const __nv_bfloat16* gB = g_weff + (size_t)bn * D_MODEL + kbase + bh * 16;
    const uint32_t bDst0 = sb + B_BASE_B + (uint32_t)bn * (BROWH * 2) + bh * 32;

#pragma unroll
    for (int s = 0; s < NST; ++s) {
        const uint32_t aD = aDst0 + s * A_STG_B;
        const uint32_t bD = bDst0 + s * B_STG_B;
        const float* aS = gA + s * KC;
        const __nv_bfloat16* bS = gB + s * KC;
#pragma unroll
        for (int q = 0; q < 8; ++q) cp16(aD + q * 16, aS + q * 4);
#pragma unroll
        for (int j = 0; j < 2; ++j) cp16(bD + j * 16, bS + j * 8);
        asm volatile("cp.async.commit_group;" ::: "memory");
    }

    for (int c = 0; c < NCHUNK; ++c) {
        const int s = c % NST;
        asm volatile("cp.async.wait_group 2;" ::: "memory");
        __syncthreads();

        const int aBaseW = s * (A_STG_B / 4) + (w * 32 + g) * AROWF;   // float idx
        const int bBaseW = s * (B_STG_B / 4);                          // word idx
#pragma unroll
        for (int kk = 0; kk < 2; ++kk) {
            const int k0 = kk * 16 + 2 * tig;
            // A fragments (fp32 -> bf16x2)
            uint32_t a[2][4];
#pragma unroll
            for (int t = 0; t < 2; ++t) {
                const int r = aBaseW + 16 * t * AROWF + k0;
                float2 p0 = *(const float2*)&smA[r];
                float2 p1 = *(const float2*)&smA[r + 8];
                float2 p2 = *(const float2*)&smA[r + 8 * AROWF];
                float2 p3 = *(const float2*)&smA[r + 8 * AROWF + 8];
                a[t][0] = pack_bf16(p0.y, p0.x);
                a[t][1] = pack_bf16(p2.y, p2.x);
                a[t][2] = pack_bf16(p1.y, p1.x);
                a[t][3] = pack_bf16(p3.y, p3.x);
            }
            // B fragments (bf16 pairs)
            uint32_t b[8][2];
#pragma unroll
            for (int n = 0; n < 8; ++n) {
                const int r = bBaseW + (8 * n + g) * (BROWH / 2) + (k0 >> 1) + kk * 8 - kk * 8; // placeholder
                // word index: n-row * 20 words + k0/2 words... compute directly:
                const int widx = bBaseW + (8 * n + g) * 20 + 8 * kk + tig;
                b[n][0] = smBu[widx];
                b[n][1] = smBu[widx + 4];
                (void)r;
            }
#pragma unroll
            for (int t = 0; t < 2; ++t)
#pragma unroll
                for (int n = 0; n < 8; ++n)
                    mma_bf16(acc[t][n], a[t], b[n]);
        }
        __syncthreads();

        const int cn = c + NST;
        if (cn < NCHUNK) {
            const uint32_t aD = aDst0 + s * A_STG_B;
            const uint32_t bD = bDst0 + s * B_STG_B;
            const float* aS = gA + cn * KC;
            const __nv_bfloat16* bS = gB + cn * KC;
#pragma unroll
            for (int q = 0; q < 8; ++q) cp16(aD + q * 16, aS + q * 4);
#pragma unroll
            for (int j = 0; j < 2; ++j) cp16(bD + j * 16, bS + j * 8);
        }
        asm volatile("cp.async.commit_group;" ::: "memory");
    }

    // write partials: [row][ks][col]
#pragma unroll
    for (int t = 0; t < 2; ++t) {
        const int row0 = rowbase + w * 32 + 16 * t + g;
#pragma unroll
        for (int n = 0; n < 8; ++n) {
            const int col = 8 * n + 2 * tig;
            *(float2*)&g_partial[((size_t)row0 * 4 + ks) * 64 + col] =
                make_float2(acc[t][n][0], acc[t][n][1]);
            *(float2*)&g_partial[((size_t)(row0 + 8) * 4 + ks) * 64 + col] =
                make_float2(acc[t][n][2], acc[t][n][3]);
        }
    }
}

// ============================================================
// Kernel 3: reduce split-K partials + GELU dot W2 + softplus -> g_delta
// ============================================================
__global__ void __launch_bounds__(256)
reduce_kernel(const float* __restrict__ b1,
              const float* __restrict__ W2,
              const float* __restrict__ b2) {
    const int w = threadIdx.x >> 5, lane = threadIdx.x & 31;
    const int row = blockIdx.x * 8 + w;
    const int col = 2 * lane;

    float2 s = make_float2(0.0f, 0.0f);
#pragma unroll
    for (int ks = 0; ks < KSPLIT; ++ks) {
        float2 p = *(const float2*)&g_partial[((size_t)row * 4 + ks) * 64 + col];
        s.x += p.x;
        s.y += p.y;
    }
    float v = gelu_exact(s.x + b1[col]) * W2[col]
            + gelu_exact(s.y + b1[col + 1]) * W2[col + 1];
#pragma unroll
    for (int off = 16; off > 0; off >>= 1)
        v += __shfl_xor_sync(0xffffffffu, v, off);
    if (lane == 0) g_delta[row] = softplus_f(v + b2[0]);
}

// ============================================================
// Kernel 4: mean + causal EMA + gate. 1 block x 512 threads.
// lane segment = 16 elems; hierarchy: lane scan -> warp scan -> warp compose
// ============================================================
__global__ void __launch_bounds__(512)
ema_kernel(const float* __restrict__ lam_p, float* __restrict__ out) {
    __shared__ float wtot[16];
    __shared__ float wsum[16];
    const int tid = threadIdx.x;
    const int warp = tid >> 5, lane = tid & 31;
    const int batch = tid >> 7;          // 0..3 (128 threads per batch)
    const int wib = (tid >> 5) & 3;      // warp in batch
    const int seg = tid & 127;           // segment in batch
    const float alpha = 0.9f, onem = 0.1f;
    const float A16 = 0.18530201888518416f;   // 0.9^16

    float d[16];
    const float4* dv = (const float4*)(g_delta + batch * SEQ + seg * 16);
#pragma unroll
    for (int q = 0; q < 4; ++q) {
        float4 x = dv[q];
        d[4 * q + 0] = x.x; d[4 * q + 1] = x.y; d[4 * q + 2] = x.z; d[4 * q + 3] = x.w;
    }

    float s = 0.0f, sum = 0.0f;
#pragma unroll
    for (int j = 0; j < 16; ++j) { s = fmaf(alpha, s, onem * d[j]); sum += d[j]; }
#pragma unroll
    for (int off = 16; off > 0; off >>= 1) sum += __shfl_xor_sync(0xffffffffu, sum, off);
    if (lane == 0) wsum[warp] = sum;

    // inclusive affine scan within warp (ratio A16 per segment)
    float t = s, Ak = A16;
#pragma unroll
    for (int off = 1; off < 32; off <<= 1) {
        float v = __shfl_up_sync(0xffffffffu, t, off);
        if (lane >= off) t = fmaf(Ak, v, t);
        Ak *= Ak;
    }
    if (lane == 31) wtot[warp] = t;
    __syncthreads();

    // cross-warp carry within batch: H = state at start of this warp's span
    const float A512 = powf(alpha, 512.0f);
    float H = 0.0f;
    for (int j = 0; j < wib; ++j) H = fmaf(A512, H, wtot[batch * 4 + j]);

    const float tprev = __shfl_up_sync(0xffffffffu, t, 1);
    const float Al = __powf(A16, (float)lane);
    float h = fmaf(H, Al, (lane > 0) ? tprev : 0.0f);  // state entering this segment

    const float lam = lam_p[0];
    float fbuf[16], gbuf[16];
#pragma unroll
    for (int j = 0; j < 16; ++j) {
        h = fmaf(alpha, h, onem * d[j]);
        fbuf[j] = h;
        gbuf[j] = __fdividef(1.0f, 1.0f + __expf(lam * h));
    }
    float4* gout = (float4*)(out + batch * SEQ + seg * 16);
    float4* fout = (float4*)(out + BS_TOT + batch * SEQ + seg * 16);
#pragma unroll
    for (int q = 0; q < 4; ++q) {
        gout[q] = make_float4(gbuf[4 * q], gbuf[4 * q + 1], gbuf[4 * q + 2], gbuf[4 * q + 3]);
        fout[q] = make_float4(fbuf[4 * q], fbuf[4 * q + 1], fbuf[4 * q + 2], fbuf[4 * q + 3]);
    }

    if (tid == 0) {
        float tot = 0.0f;
#pragma unroll
        for (int j = 0; j < 16; ++j) tot += wsum[j];
        out[2 * BS_TOT] = tot * (1.0f / (float)BS_TOT);
    }
}

// ============================================================
extern "C" void kernel_launch(void* const* d_in, const int* in_sizes, int n_in,
                              void* d_out, int out_size) {
    const float* hidden = (const float*)d_in[0];
    const float* Wf     = (const float*)d_in[1];
    const float* W1     = (const float*)d_in[2];
    const float* b1     = (const float*)d_in[3];
    const float* W2     = (const float*)d_in[4];
    const float* b2     = (const float*)d_in[5];
    const float* lam    = (const float*)d_in[6];
    float* out = (float*)d_out;

    static int inited = 0;
    if (!inited) {
        cudaFuncSetAttribute(gemm_mma_kernel,
                             cudaFuncAttributeMaxDynamicSharedMemorySize, SMEM_B);
        inited = 1;
    }

    weff_kernel<<<dim3(4, D_CTRL), 256>>>(W1, Wf);
    gemm_mma_kernel<<<dim3(BS_TOT / MTILE, KSPLIT), 128, SMEM_B>>>(hidden);
    reduce_kernel<<<BS_TOT / 8, 256>>>(b1, W2, b2);
    ema_kernel<<<1, 512>>>(lam, out);
}